// round 3
// baseline (speedup 1.0000x reference)
#include <cuda_runtime.h>

#define DTc 0.05f

// global scratch (static device arrays; no allocation)
__device__ float g_s2  [64*256*64];
__device__ float g_xres[64*256*64];
__device__ float g_K   [64*256*16*64];
__device__ float g_kv  [64*256*16];
__device__ float g_s   [64*256*64];
__device__ float g_P   [(size_t)64*256*64*64];

// C(64x64) = [A1] + [A2] + alpha * L' @ R'   (row-major, 256 threads, 4x4 tiles)
// SMODE 0: plain; 1: L col-scaled by s[j]; 2: R row-scaled by s[j]
template<int SMODE>
__device__ __forceinline__ void gemm64t(float* __restrict__ C,
    const float* __restrict__ L, const float* __restrict__ R,
    const float* __restrict__ s, float alpha,
    const float* __restrict__ A1, const float* __restrict__ A2)
{
    const int tid = threadIdx.x;
    const int c0 = (tid & 15) * 4, r0 = (tid >> 4) * 4;
    float acc[4][4];
#pragma unroll
    for (int r = 0; r < 4; r++) { acc[r][0]=0.f; acc[r][1]=0.f; acc[r][2]=0.f; acc[r][3]=0.f; }
#pragma unroll 4
    for (int jj = 0; jj < 16; jj++) {
        float sv0=1.f, sv1=1.f, sv2=1.f, sv3=1.f;
        if (SMODE) { float4 t = *(const float4*)(s + jj*4); sv0=t.x; sv1=t.y; sv2=t.z; sv3=t.w; }
        float4 lv[4], rv[4];
#pragma unroll
        for (int r = 0; r < 4; r++) {
            lv[r] = *(const float4*)(L + (r0+r)*64 + jj*4);
            if (SMODE == 1) { lv[r].x*=sv0; lv[r].y*=sv1; lv[r].z*=sv2; lv[r].w*=sv3; }
        }
#pragma unroll
        for (int q = 0; q < 4; q++) rv[q] = *(const float4*)(R + (jj*4+q)*64 + c0);
        if (SMODE == 2) {
            rv[0].x*=sv0; rv[0].y*=sv0; rv[0].z*=sv0; rv[0].w*=sv0;
            rv[1].x*=sv1; rv[1].y*=sv1; rv[1].z*=sv1; rv[1].w*=sv1;
            rv[2].x*=sv2; rv[2].y*=sv2; rv[2].z*=sv2; rv[2].w*=sv2;
            rv[3].x*=sv3; rv[3].y*=sv3; rv[3].z*=sv3; rv[3].w*=sv3;
        }
#pragma unroll
        for (int r = 0; r < 4; r++) {
            const float* lp = (const float*)&lv[r];
#pragma unroll
            for (int q = 0; q < 4; q++) {
                const float l = lp[q];
                acc[r][0] = fmaf(l, rv[q].x, acc[r][0]);
                acc[r][1] = fmaf(l, rv[q].y, acc[r][1]);
                acc[r][2] = fmaf(l, rv[q].z, acc[r][2]);
                acc[r][3] = fmaf(l, rv[q].w, acc[r][3]);
            }
        }
    }
#pragma unroll
    for (int r = 0; r < 4; r++) {
        const int base = (r0+r)*64 + c0;
#pragma unroll
        for (int c = 0; c < 4; c++) {
            float v = alpha * acc[r][c];
            if (A1) v += A1[base+c];
            if (A2) v += A2[base+c];
            C[base+c] = v;
        }
    }
}

// C(64x16) = [A1] + alpha * L'(64x64) @ R'(64x16); thread = 4 rows x 1 col
// SMODE 1: L col-scaled by s[j]; 2: R row-scaled by s[j]
template<int SMODE>
__device__ __forceinline__ void gemm6416t(float* __restrict__ C,
    const float* __restrict__ L, const float* __restrict__ R,
    const float* __restrict__ s, float alpha, const float* __restrict__ A1)
{
    const int tid = threadIdx.x;
    const int c = tid & 15, r0 = (tid >> 4) * 4;
    float acc[4] = {0.f,0.f,0.f,0.f};
#pragma unroll 4
    for (int jj = 0; jj < 16; jj++) {
        float sv0=1.f, sv1=1.f, sv2=1.f, sv3=1.f;
        if (SMODE) { float4 t = *(const float4*)(s + jj*4); sv0=t.x; sv1=t.y; sv2=t.z; sv3=t.w; }
        float4 lv[4];
#pragma unroll
        for (int r = 0; r < 4; r++) {
            lv[r] = *(const float4*)(L + (r0+r)*64 + jj*4);
            if (SMODE == 1) { lv[r].x*=sv0; lv[r].y*=sv1; lv[r].z*=sv2; lv[r].w*=sv3; }
        }
        float rq[4];
#pragma unroll
        for (int q = 0; q < 4; q++) {
            rq[q] = R[(jj*4+q)*16 + c];
        }
        if (SMODE == 2) { rq[0]*=sv0; rq[1]*=sv1; rq[2]*=sv2; rq[3]*=sv3; }
#pragma unroll
        for (int q = 0; q < 4; q++) {
            acc[0] = fmaf(((const float*)&lv[0])[q], rq[q], acc[0]);
            acc[1] = fmaf(((const float*)&lv[1])[q], rq[q], acc[1]);
            acc[2] = fmaf(((const float*)&lv[2])[q], rq[q], acc[2]);
            acc[3] = fmaf(((const float*)&lv[3])[q], rq[q], acc[3]);
        }
    }
#pragma unroll
    for (int r = 0; r < 4; r++) {
        float v = alpha * acc[r];
        if (A1) v += A1[(r0+r)*16 + c];
        C[(r0+r)*16 + c] = v;
    }
}

// C(64x64) = A1 + L(64x16) @ R(16x64); in-place safe when C == A1
__device__ __forceinline__ void gemmPn(float* __restrict__ C, const float* __restrict__ L,
                                       const float* __restrict__ R, const float* __restrict__ A1)
{
    const int tid = threadIdx.x;
    const int c0 = (tid & 15) * 4, r0 = (tid >> 4) * 4;
    float acc[4][4];
#pragma unroll
    for (int r = 0; r < 4; r++) { acc[r][0]=0.f; acc[r][1]=0.f; acc[r][2]=0.f; acc[r][3]=0.f; }
#pragma unroll
    for (int jj = 0; jj < 4; jj++) {
        float4 lv[4], rv[4];
#pragma unroll
        for (int r = 0; r < 4; r++) lv[r] = *(const float4*)(L + (r0+r)*16 + jj*4);
#pragma unroll
        for (int q = 0; q < 4; q++) rv[q] = *(const float4*)(R + (jj*4+q)*64 + c0);
#pragma unroll
        for (int r = 0; r < 4; r++) {
            const float* lp = (const float*)&lv[r];
#pragma unroll
            for (int q = 0; q < 4; q++) {
                const float l = lp[q];
                acc[r][0] = fmaf(l, rv[q].x, acc[r][0]);
                acc[r][1] = fmaf(l, rv[q].y, acc[r][1]);
                acc[r][2] = fmaf(l, rv[q].z, acc[r][2]);
                acc[r][3] = fmaf(l, rv[q].w, acc[r][3]);
            }
        }
    }
#pragma unroll
    for (int r = 0; r < 4; r++) {
        const int base = (r0+r)*64 + c0;
#pragma unroll
        for (int c = 0; c < 4; c++) C[base+c] = A1[base+c] + acc[r][c];
    }
}

__global__ void __launch_bounds__(256, 2) mpc_kernel(
    const float* __restrict__ x0_in, const float* __restrict__ x_in,
    const float* __restrict__ u_in,  const float* __restrict__ lmd_in,
    const float* __restrict__ A_in,  const float* __restrict__ Bm_in,
    const float* __restrict__ Qx_in, const float* __restrict__ R_in,
    const float* __restrict__ Vf_in, const float* __restrict__ xref_in,
    float* __restrict__ out)
{
    extern __shared__ float sh[];
    float* sA   = sh;           float* sAT  = sA+4096;   float* sQx = sAT+4096;
    float* sP   = sQx+4096;     float* sM1  = sP+4096;
    float* sBm  = sM1+4096;     float* sBmT = sBm+1024;  float* sPFu= sBmT+1024;
    float* sQxu = sPFu+1024;    float* sK   = sQxu+1024;
    float* sR   = sK+1024;      float* sQuu = sR+256;    float* sInv= sQuu+272;
    float* vxref= sInv+272;
    float* vrN  = vxref+64; float* vx0r = vrN+64;  float* vs2  = vx0r+64;
    float* vxres= vs2+64;   float* vsv  = vxres+64;float* vxn  = vsv+64;
    float* vxn1 = vxn+64;   float* vlmd0= vxn1+64; float* vlmd1= vlmd0+64;
    float* vq   = vlmd1+64; float* vxmr = vq+64;   float* vrx  = vxmr+64;
    float* vv   = vrx+64;   float* vq2  = vv+64;   float* vlx  = vq2+64;
    float* vdx  = vlx+64;   float* vdxn = vdx+64;
    float* vu   = vdxn+64;  float* vru  = vu+16;   float* vlu  = vru+16;
    float* vkk  = vlu+16;   float* vdu  = vkk+16;

    const int tid = threadIdx.x, b = blockIdx.x;
    float* xw = out;
    float* uw = out + 65*256*64;
    float* lw = uw  + 64*256*16;

    for (int e = tid; e < 4096; e += 256) {
        float a = A_in[e];
        sA[e] = a; sQx[e] = Qx_in[e];
        int i = e >> 6, j = e & 63;
        sAT[j*64+i] = a;
    }
    for (int e = tid; e < 1024; e += 256) {
        float v = Bm_in[e]; sBm[e] = v;
        int j = e >> 4, i = e & 15;
        sBmT[i*64+j] = v;
    }
    sR[tid] = R_in[tid];
    if (tid < 64) vxref[tid] = xref_in[tid];
    for (int e = tid; e < 65*64; e += 256) {
        int n = e >> 6, i = e & 63;
        int idx = (n*256 + b)*64 + i;
        xw[idx] = x_in[idx]; lw[idx] = lmd_in[idx];
    }
    for (int e = tid; e < 64*16; e += 256) {
        int n = e >> 4, i = e & 15;
        int idx = (n*256 + b)*16 + i;
        uw[idx] = u_in[idx];
    }
    __syncthreads();

    for (int iter = 0; iter < 2; iter++) {
        // terminal: P_N = Vf, rN = Vf(x_N - xref) - lmd_N, s_N = rN
        for (int e = tid; e < 4096; e += 256) sP[e] = Vf_in[e];
        if (tid < 64) {
            vxn[tid]  = xw[(64*256 + b)*64 + tid];
            vx0r[tid] = xw[b*64 + tid] - x0_in[b*64 + tid];
        }
        __syncthreads();
        if (tid < 64) {
            const int j = tid; float acc = 0.f;
#pragma unroll 8
            for (int i = 0; i < 64; i++) acc = fmaf(sP[i*64+j], vxn[i]-vxref[i], acc);
            float r = acc - lw[(64*256 + b)*64 + j];
            vrN[j] = r; vsv[j] = r;
        }
        __syncthreads();

        // ---------------- backward Riccati ----------------
        for (int n = 63; n >= 0; n--) {
            const int ofs = n*256 + b;
            // S0: load step vectors
            if (tid < 64) {
                vxn[tid]   = xw[ofs*64 + tid];
                vxn1[tid]  = xw[(ofs+256)*64 + tid];
                vlmd0[tid] = lw[ofs*64 + tid];
                vlmd1[tid] = lw[(ofs+256)*64 + tid];
            } else if (tid < 80) {
                vu[tid-64] = uw[ofs*16 + tid-64];
            }
            __syncthreads();
            // S1: z, s2, xres, q, xmr
            if (tid < 64) {
                const int j = tid; float z = 0.f;
#pragma unroll 8
                for (int i = 0; i < 64; i++) z = fmaf(sAT[i*64+j], vxn[i], z);
#pragma unroll
                for (int i = 0; i < 16; i++) z = fmaf(sBmT[i*64+j], vu[i], z);
                float t = tanhf(z), s2 = 1.f - t*t;
                vs2[j] = s2;
                float xr = vxn[j] + DTc*t - vxn1[j];
                vxres[j] = xr;
                vq[j]   = s2 * vlmd1[j];
                vxmr[j] = vxn[j] - vxref[j];
                g_s2[ofs*64+j] = s2; g_xres[ofs*64+j] = xr;
            }
            __syncthreads();
            // S2: PFx = P + DT*(P .*col s2)@A ; PFu = DT*(P .*col s2)@Bm
            gemm64t<1>(sM1, sP, sA, vs2, DTc, sP, 0);
            gemm6416t<1>(sPFu, sP, sBm, vs2, DTc, 0);
            __syncthreads();
            // S3: rx, ru, v, q2 (disjoint thread ranges; sP still old P)
            if (tid < 64) {
                const int j = tid; float a1 = 0.f, a2 = 0.f;
#pragma unroll 8
                for (int i = 0; i < 64; i++) {
                    a1 = fmaf(sQx[i*64+j], vxmr[i], a1);
                    a2 = fmaf(sA[i*64+j],  vq[i],   a2);
                }
                vrx[j] = a1 + vlmd1[j] + DTc*a2 - vlmd0[j];
            } else if (tid < 80) {
                const int j = tid - 64; float a1 = 0.f, a2 = 0.f;
#pragma unroll
                for (int i = 0; i < 16; i++) a1 = fmaf(sR[i*16+j], vu[i], a1);
#pragma unroll 8
                for (int i = 0; i < 64; i++) a2 = fmaf(sBm[i*16+j], vq[i], a2);
                vru[j] = a1 + DTc*a2;
            } else if (tid >= 128 && tid < 192) {
                const int j = tid - 128; float acc = 0.f;
#pragma unroll 8
                for (int i = 0; i < 64; i++) acc = fmaf(sP[i*64+j], vxres[i], acc);
                float vv_ = acc + vsv[j];
                vv[j] = vv_; vq2[j] = vs2[j] * vv_;
            }
            __syncthreads();
            // S4: Qxx -> sP (old P dead), Qxu, Quu
            gemm64t<2>(sP, sAT, sM1, vs2, DTc, sQx, sM1);        // Qxx = Qx + PFx + DT*AT@(s2.*row PFx)
            gemm6416t<2>(sQxu, sAT, sPFu, vs2, DTc, sPFu);       // Qxu = PFu + DT*AT@(s2.*row PFu)
            {
                const int i = tid >> 4, k = tid & 15; float acc = 0.f;
#pragma unroll 8
                for (int j = 0; j < 64; j++) acc = fmaf(sBmT[i*64+j], vs2[j]*sPFu[j*16+k], acc);
                sQuu[i*17+k] = sR[i*16+k] + DTc*acc;             // Quu = R + DT*BmT@(s2.*row PFu)
            }
            __syncthreads();
            // S5: warp 0 -> register/shuffle Gauss-Jordan inverse of Quu (SPD);
            //     tids 64..127 -> lx; tids 128..143 -> lu (all concurrent)
            if (tid < 32) {
                const int lane = tid;
                float creg[16];
#pragma unroll
                for (int r = 0; r < 16; r++)
                    creg[r] = (lane < 16) ? sQuu[r*17 + lane] : ((r == lane-16) ? 1.f : 0.f);
#pragma unroll
                for (int p = 0; p < 16; p++) {
                    float piv = __shfl_sync(0xffffffffu, creg[p], p);
                    float newp = creg[p] * (1.0f / piv);
#pragma unroll
                    for (int r = 0; r < 16; r++) {
                        if (r == p) continue;
                        float fac = __shfl_sync(0xffffffffu, creg[r], p);
                        creg[r] = fmaf(-fac, newp, creg[r]);
                    }
                    creg[p] = newp;
                }
                if (lane >= 16) {
#pragma unroll
                    for (int r = 0; r < 16; r++) sInv[r*17 + (lane-16)] = creg[r];
                }
            } else if (tid >= 64 && tid < 128) {
                const int j = tid - 64; float acc = 0.f;
#pragma unroll 8
                for (int i = 0; i < 64; i++) acc = fmaf(sA[i*64+j], vq2[i], acc);
                vlx[j] = vrx[j] + vv[j] + DTc*acc;
            } else if (tid >= 128 && tid < 144) {
                const int j = tid - 128; float acc = 0.f;
#pragma unroll 8
                for (int i = 0; i < 64; i++) acc = fmaf(sBm[i*16+j], vq2[i], acc);
                vlu[j] = vru[j] + DTc*acc;
            }
            __syncthreads();
            // S6: K = -Inv @ Qxu^T (all 256), k = -Inv @ lu (tid<16, independent)
            {
                const int i = tid & 15, m0 = (tid >> 4) * 4;
                float a0=0.f,a1=0.f,a2=0.f,a3=0.f;
#pragma unroll
                for (int j = 0; j < 16; j++) {
                    const float iv = sInv[i*17+j];
                    a0 = fmaf(iv, sQxu[(m0+0)*16+j], a0);
                    a1 = fmaf(iv, sQxu[(m0+1)*16+j], a1);
                    a2 = fmaf(iv, sQxu[(m0+2)*16+j], a2);
                    a3 = fmaf(iv, sQxu[(m0+3)*16+j], a3);
                }
                sK[i*64+m0]=-a0; sK[i*64+m0+1]=-a1; sK[i*64+m0+2]=-a2; sK[i*64+m0+3]=-a3;
            }
            if (tid < 16) {
                float a = 0.f;
#pragma unroll
                for (int j = 0; j < 16; j++) a = fmaf(sInv[tid*17+j], vlu[j], a);
                vkk[tid] = -a;
            }
            __syncthreads();
            // S7: Pn = Qxx + Qxu@K, in place into sP
            gemmPn(sP, sQxu, sK, sP);
            __syncthreads();
            // S8: symmetrize in place (pair ownership), sn, kv store
            for (int e = tid; e < 4096; e += 256) {
                int i = e >> 6, j = e & 63;
                if (i < j) {
                    float a = sP[i*64+j], bb = sP[j*64+i];
                    float m = 0.5f * (a + bb);
                    sP[i*64+j] = m; sP[j*64+i] = m;
                }
            }
            if (tid < 64) {
                const int j = tid; float a = vlx[j];
#pragma unroll
                for (int i = 0; i < 16; i++) a = fmaf(sQxu[j*16+i], vkk[i], a);
                vsv[j] = a; g_s[ofs*64+j] = a;
            } else if (tid < 80) {
                g_kv[ofs*16 + tid-64] = vkk[tid-64];
            }
            __syncthreads();
            // S9: spill P, K to global for forward pass
            for (int e = tid; e < 1024; e += 256)
                ((float4*)(g_P + (size_t)ofs*4096))[e] = ((const float4*)sP)[e];
            ((float4*)(g_K + (size_t)ofs*1024))[tid] = ((const float4*)sK)[tid];
            __syncthreads();
        }

        // ---------------- forward rollout ----------------
        if (tid < 64) vdx[tid] = -vx0r[tid];
        __syncthreads();
        for (int n = 0; n < 64; n++) {
            const int ofs = n*256 + b;
            for (int e = tid; e < 1024; e += 256)
                ((float4*)sM1)[e] = ((const float4*)(g_P + (size_t)ofs*4096))[e];
            ((float4*)sK)[tid] = ((const float4*)(g_K + (size_t)ofs*1024))[tid];
            if (tid < 64) { vs2[tid] = g_s2[ofs*64+tid]; vxres[tid] = g_xres[ofs*64+tid]; }
            __syncthreads();
            if (tid < 16) {
                float a = g_kv[ofs*16 + tid];
#pragma unroll 8
                for (int m = 0; m < 64; m++) {
                    int mm = (tid*4 + m) & 63;
                    a = fmaf(sK[tid*64+mm], vdx[mm], a);
                }
                vdu[tid] = a;
            }
            __syncthreads();
            if (tid < 64) {
                const int j = tid; float adx = 0.f, pdx = 0.f, bdu = 0.f;
#pragma unroll 8
                for (int i = 0; i < 64; i++) {
                    adx = fmaf(sAT[i*64+j], vdx[i], adx);
                    pdx = fmaf(sM1[i*64+j], vdx[i], pdx);
                }
#pragma unroll
                for (int i = 0; i < 16; i++) bdu = fmaf(sBmT[i*64+j], vdu[i], bdu);
                vdxn[j] = vdx[j] + DTc*vs2[j]*(adx + bdu) + vxres[j];
                const int idx = ofs*64 + j;
                xw[idx] += vdx[j];
                lw[idx] += pdx + g_s[ofs*64+j];
            } else if (tid < 80) {
                uw[ofs*16 + tid-64] += vdu[tid-64];
            }
            __syncthreads();
            if (tid < 64) vdx[tid] = vdxn[tid];
            __syncthreads();
        }
        // terminal: dlmd_N = Vf dxN + rN
        if (tid < 64) {
            const int j = tid; float p = 0.f;
#pragma unroll 8
            for (int i = 0; i < 64; i++) p = fmaf(Vf_in[i*64+j], vdx[i], p);
            const int idx = (64*256 + b)*64 + j;
            xw[idx] += vdx[j];
            lw[idx] += p + vrN[j];
        }
        __syncthreads();
    }
}

extern "C" void kernel_launch(void* const* d_in, const int* in_sizes, int n_in,
                              void* d_out, int out_size) {
    const float* x0   = (const float*)d_in[0];
    const float* x    = (const float*)d_in[1];
    const float* u    = (const float*)d_in[2];
    const float* lmd  = (const float*)d_in[3];
    const float* A    = (const float*)d_in[4];
    const float* Bm   = (const float*)d_in[5];
    const float* Qx   = (const float*)d_in[6];
    const float* R    = (const float*)d_in[7];
    const float* Vf   = (const float*)d_in[8];
    const float* Vfv  = Vf; (void)Vfv;
    const float* xref = (const float*)d_in[9];
    const int smem_bytes = 110528;
    cudaFuncSetAttribute(mpc_kernel, cudaFuncAttributeMaxDynamicSharedMemorySize, smem_bytes);
    mpc_kernel<<<256, 256, smem_bytes>>>(x0, x, u, lmd, A, Bm, Qx, R, Vf, xref, (float*)d_out);
}

// round 4
// speedup vs baseline: 1.5679x; 1.5679x over previous
#include <cuda_runtime.h>

#define DTc 0.05f
typedef unsigned long long ull;

// global scratch (static device arrays; no allocation)
__device__ float g_s2  [64*256*64];
__device__ float g_xres[64*256*64];
__device__ float g_K   [64*256*16*64];
__device__ float g_kv  [64*256*16];
__device__ float g_s   [64*256*64];
__device__ float g_P   [(size_t)64*256*64*64];

__device__ __forceinline__ ull pack2(float x, float y) {
    ull r; asm("mov.b64 %0, {%1, %2};" : "=l"(r) : "f"(x), "f"(y)); return r;
}
__device__ __forceinline__ void unpack2(ull v, float& x, float& y) {
    asm("mov.b64 {%0, %1}, %2;" : "=f"(x), "=f"(y) : "l"(v));
}
__device__ __forceinline__ void ffma2(ull& d, ull a, ull b) {
    asm("fma.rn.f32x2 %0, %1, %2, %0;" : "+l"(d) : "l"(a), "l"(b));
}

// C(64x64) = [A1] + [A2] + alpha * (L K-scaled-by-s) @ R. 256 thr, 4x4 tiles, f32x2.
template<bool SCALE>
__device__ __forceinline__ void gemm64f2(float* __restrict__ C,
    const float* __restrict__ L, const float* __restrict__ R,
    const float* __restrict__ s, float alpha,
    const float* __restrict__ A1, const float* __restrict__ A2)
{
    const int tid = threadIdx.x;
    const int c0 = (tid & 15) * 4, r0 = (tid >> 4) * 4;
    ull acc[4][2];
#pragma unroll
    for (int r = 0; r < 4; r++) { acc[r][0] = 0ull; acc[r][1] = 0ull; }
#pragma unroll 4
    for (int jj = 0; jj < 16; jj++) {
        float4 sv4;
        if (SCALE) sv4 = *(const float4*)(s + jj*4);
        const float* sp = (const float*)&sv4;
        float4 lv[4], rv[4];
#pragma unroll
        for (int r = 0; r < 4; r++) lv[r] = *(const float4*)(L + (r0+r)*64 + jj*4);
#pragma unroll
        for (int q = 0; q < 4; q++) rv[q] = *(const float4*)(R + (jj*4+q)*64 + c0);
        ull rp[4][2];
#pragma unroll
        for (int q = 0; q < 4; q++) {
            rp[q][0] = pack2(rv[q].x, rv[q].y);
            rp[q][1] = pack2(rv[q].z, rv[q].w);
        }
#pragma unroll
        for (int r = 0; r < 4; r++) {
            const float* lp = (const float*)&lv[r];
#pragma unroll
            for (int q = 0; q < 4; q++) {
                float m = SCALE ? lp[q]*sp[q] : lp[q];
                ull lb = pack2(m, m);
                ffma2(acc[r][0], lb, rp[q][0]);
                ffma2(acc[r][1], lb, rp[q][1]);
            }
        }
    }
#pragma unroll
    for (int r = 0; r < 4; r++) {
        float o[4];
        unpack2(acc[r][0], o[0], o[1]);
        unpack2(acc[r][1], o[2], o[3]);
        const int base = (r0+r)*64 + c0;
#pragma unroll
        for (int c = 0; c < 4; c++) {
            float v = alpha * o[c];
            if (A1) v += A1[base+c];
            if (A2) v += A2[base+c];
            C[base+c] = v;
        }
    }
}

// C(64x16) = [A1] + alpha * (L K-scaled-by-s)(64x64) @ R(64x16). f32x2 pairs along rows.
template<bool SCALE>
__device__ __forceinline__ void gemm6416f2(float* __restrict__ C,
    const float* __restrict__ L, const float* __restrict__ R,
    const float* __restrict__ s, float alpha, const float* __restrict__ A1)
{
    const int tid = threadIdx.x;
    const int c = tid & 15, r0 = (tid >> 4) * 4;
    ull acc01 = 0ull, acc23 = 0ull;
#pragma unroll 4
    for (int jj = 0; jj < 16; jj++) {
        float4 sv4;
        if (SCALE) sv4 = *(const float4*)(s + jj*4);
        const float* sp = (const float*)&sv4;
        float4 lv[4];
#pragma unroll
        for (int r = 0; r < 4; r++) lv[r] = *(const float4*)(L + (r0+r)*64 + jj*4);
#pragma unroll
        for (int q = 0; q < 4; q++) {
            float rb = R[(jj*4+q)*16 + c];
            ull rbb = pack2(rb, rb);
            float f0 = ((const float*)&lv[0])[q], f1 = ((const float*)&lv[1])[q];
            float f2 = ((const float*)&lv[2])[q], f3 = ((const float*)&lv[3])[q];
            if (SCALE) { f0*=sp[q]; f1*=sp[q]; f2*=sp[q]; f3*=sp[q]; }
            ffma2(acc01, pack2(f0, f1), rbb);
            ffma2(acc23, pack2(f2, f3), rbb);
        }
    }
    float o[4];
    unpack2(acc01, o[0], o[1]);
    unpack2(acc23, o[2], o[3]);
#pragma unroll
    for (int r = 0; r < 4; r++) {
        float v = alpha * o[r];
        if (A1) v += A1[(r0+r)*16 + c];
        C[(r0+r)*16 + c] = v;
    }
}

// C(64x64) = A1 + L(64x16) @ R(16x64); in-place safe when C == A1
__device__ __forceinline__ void gemmPnf2(float* __restrict__ C, const float* __restrict__ L,
                                         const float* __restrict__ R, const float* __restrict__ A1)
{
    const int tid = threadIdx.x;
    const int c0 = (tid & 15) * 4, r0 = (tid >> 4) * 4;
    ull acc[4][2];
#pragma unroll
    for (int r = 0; r < 4; r++) { acc[r][0] = 0ull; acc[r][1] = 0ull; }
#pragma unroll
    for (int jj = 0; jj < 4; jj++) {
        float4 lv[4], rv[4];
#pragma unroll
        for (int r = 0; r < 4; r++) lv[r] = *(const float4*)(L + (r0+r)*16 + jj*4);
#pragma unroll
        for (int q = 0; q < 4; q++) rv[q] = *(const float4*)(R + (jj*4+q)*64 + c0);
        ull rp[4][2];
#pragma unroll
        for (int q = 0; q < 4; q++) {
            rp[q][0] = pack2(rv[q].x, rv[q].y);
            rp[q][1] = pack2(rv[q].z, rv[q].w);
        }
#pragma unroll
        for (int r = 0; r < 4; r++) {
            const float* lp = (const float*)&lv[r];
#pragma unroll
            for (int q = 0; q < 4; q++) {
                ull lb = pack2(lp[q], lp[q]);
                ffma2(acc[r][0], lb, rp[q][0]);
                ffma2(acc[r][1], lb, rp[q][1]);
            }
        }
    }
#pragma unroll
    for (int r = 0; r < 4; r++) {
        float o[4];
        unpack2(acc[r][0], o[0], o[1]);
        unpack2(acc[r][1], o[2], o[3]);
        const int base = (r0+r)*64 + c0;
#pragma unroll
        for (int c = 0; c < 4; c++) C[base+c] = A1[base+c] + o[c];
    }
}

__global__ void __launch_bounds__(256, 2) mpc_kernel(
    const float* __restrict__ x0_in, const float* __restrict__ x_in,
    const float* __restrict__ u_in,  const float* __restrict__ lmd_in,
    const float* __restrict__ A_in,  const float* __restrict__ Bm_in,
    const float* __restrict__ Qx_in, const float* __restrict__ R_in,
    const float* __restrict__ Vf_in, const float* __restrict__ xref_in,
    float* __restrict__ out)
{
    extern __shared__ float sh[];
    float* sA   = sh;            float* sAT  = sA+4096;   float* sQx = sAT+4096;
    float* sP   = sQx+4096;      float* sM1  = sP+4096;
    float* sBm  = sM1+4096;      float* sBmT = sBm+1024;  float* sPFu= sBmT+1024;
    float* sQxu = sPFu+1024;     float* sK   = sQxu+1024;
    float* sR   = sK+1024;       float* sRed = sR+256;    float* sRedB = sRed+256;
    float* sRedC= sRedB+256;     // 64
    float* vxref= sRedC+64;
    float* vrN  = vxref+64; float* vx0r = vrN+64;  float* vs2  = vx0r+64;
    float* vxres= vs2+64;   float* vsv  = vxres+64;float* vxn  = vsv+64;
    float* vxn1 = vxn+64;   float* vlmd0= vxn1+64; float* vlmd1= vlmd0+64;
    float* vq   = vlmd1+64; float* vxmr = vq+64;   float* vrx  = vxmr+64;
    float* vv   = vrx+64;   float* vq2  = vv+64;   float* vlx  = vq2+64;
    float* vdx  = vlx+64;
    float* sQI  = vdx+64;   // 272 (17-stride: Quu then Inv)
    float* vu   = sQI+272;  float* vru  = vu+16;   float* vlu  = vru+16;
    float* vkk  = vlu+16;   float* vdu  = vkk+16;

    const int tid = threadIdx.x, b = blockIdx.x;
    float* xw = out;
    float* uw = out + 65*256*64;
    float* lw = uw  + 64*256*16;

    for (int e = tid; e < 4096; e += 256) {
        float a = A_in[e];
        sA[e] = a; sQx[e] = Qx_in[e];
        int i = e >> 6, j = e & 63;
        sAT[j*64+i] = a;
    }
    for (int e = tid; e < 1024; e += 256) {
        float v = Bm_in[e]; sBm[e] = v;
        int j = e >> 4, i = e & 15;
        sBmT[i*64+j] = v;
    }
    sR[tid] = R_in[tid];
    if (tid < 64) vxref[tid] = xref_in[tid];
    for (int e = tid; e < 65*64; e += 256) {
        int n = e >> 6, i = e & 63;
        int idx = (n*256 + b)*64 + i;
        xw[idx] = x_in[idx]; lw[idx] = lmd_in[idx];
    }
    for (int e = tid; e < 64*16; e += 256) {
        int n = e >> 4, i = e & 15;
        int idx = (n*256 + b)*16 + i;
        uw[idx] = u_in[idx];
    }
    __syncthreads();

    for (int iter = 0; iter < 2; iter++) {
        // terminal: P_N = Vf, rN = Vf(x_N - xref) - lmd_N, s_N = rN
        for (int e = tid; e < 4096; e += 256) sP[e] = Vf_in[e];
        if (tid < 64) {
            vxn[tid]  = xw[(64*256 + b)*64 + tid];
            vx0r[tid] = xw[b*64 + tid] - x0_in[b*64 + tid];
        }
        __syncthreads();
        if (tid < 64) {
            const int j = tid; float acc = 0.f;
#pragma unroll 8
            for (int i = 0; i < 64; i++) acc = fmaf(sP[i*64+j], vxn[i]-vxref[i], acc);
            float r = acc - lw[(64*256 + b)*64 + j];
            vrN[j] = r; vsv[j] = r;
        }
        __syncthreads();

        // ---------------- backward Riccati ----------------
        for (int n = 63; n >= 0; n--) {
            const int ofs = n*256 + b;
            // S0: load step vectors
            if (tid < 64) {
                vxn[tid]   = xw[ofs*64 + tid];
                vxn1[tid]  = xw[(ofs+256)*64 + tid];
                vlmd0[tid] = lw[ofs*64 + tid];
                vlmd1[tid] = lw[(ofs+256)*64 + tid];
            } else if (tid < 80) {
                vu[tid-64] = uw[ofs*16 + tid-64];
            }
            __syncthreads();
            // S1a: z partials (4-way split, all 256 threads)
            {
                const int j = tid & 63, qt = tid >> 6;
                float a = 0.f;
#pragma unroll
                for (int s = 0; s < 16; s++) {
                    int i = qt*16 + s;
                    a = fmaf(sAT[i*64+j], vxn[i], a);
                }
                if (qt == 3) {
#pragma unroll
                    for (int i = 0; i < 16; i++) a = fmaf(sBmT[i*64+j], vu[i], a);
                }
                sRed[qt*64+j] = a;
            }
            __syncthreads();
            // S1b: finish z -> s2, xres, q, xmr
            if (tid < 64) {
                const int j = tid;
                float z = sRed[j] + sRed[64+j] + sRed[128+j] + sRed[192+j];
                float t = tanhf(z), s2 = 1.f - t*t;
                vs2[j] = s2;
                float xr = vxn[j] + DTc*t - vxn1[j];
                vxres[j] = xr;
                vq[j]   = s2 * vlmd1[j];
                vxmr[j] = vxn[j] - vxref[j];
                g_s2[ofs*64+j] = s2; g_xres[ofs*64+j] = xr;
            }
            __syncthreads();
            // S2: PFx = P + DT*(P col-scaled s2)@A -> sM1 ; PFu = DT*(P col-scaled)@Bm
            gemm64f2<true>(sM1, sP, sA, vs2, DTc, sP, 0);
            gemm6416f2<true>(sPFu, sP, sBm, vs2, DTc, 0);
            __syncthreads();
            // S3: rx / ru / v,q2 (grouped; sP still old P)
            if (tid < 64) {
                const int j = tid; float a1 = 0.f, a2 = 0.f;
#pragma unroll 8
                for (int i = 0; i < 64; i++) {
                    a1 = fmaf(sQx[i*64+j], vxmr[i], a1);
                    a2 = fmaf(sA[i*64+j],  vq[i],   a2);
                }
                vrx[j] = a1 + vlmd1[j] + DTc*a2 - vlmd0[j];
            } else if (tid < 80) {
                const int j = tid - 64; float a1 = 0.f, a2 = 0.f;
#pragma unroll
                for (int i = 0; i < 16; i++) a1 = fmaf(sR[i*16+j], vu[i], a1);
#pragma unroll 8
                for (int i = 0; i < 64; i++) a2 = fmaf(sBm[i*16+j], vq[i], a2);
                vru[j] = a1 + DTc*a2;
            } else if (tid >= 128 && tid < 192) {
                const int j = tid - 128; float acc = 0.f;
#pragma unroll 8
                for (int i = 0; i < 64; i++) acc = fmaf(sP[i*64+j], vxres[i], acc);
                float vv_ = acc + vsv[j];
                vv[j] = vv_; vq2[j] = vs2[j] * vv_;
            }
            __syncthreads();
            // S4: Qxx -> sP (old P dead), Qxu, Quu   (K-dim s2 fold in all)
            gemm64f2<true>(sP, sAT, sM1, vs2, DTc, sQx, sM1);
            gemm6416f2<true>(sQxu, sAT, sPFu, vs2, DTc, sPFu);
            {
                const int i = tid >> 4, k = tid & 15; float acc = 0.f;
#pragma unroll 8
                for (int j = 0; j < 64; j++) acc = fmaf(sBmT[i*64+j]*vs2[j], sPFu[j*16+k], acc);
                sQI[i*17+k] = sR[i*16+k] + DTc*acc;  // Quu
            }
            __syncthreads();
            // S5: warp0 shuffle Gauss-Jordan inverse of Quu  ||  lx  ||  lu
            if (tid < 32) {
                const int lane = tid;
                float creg[16];
#pragma unroll
                for (int r = 0; r < 16; r++)
                    creg[r] = (lane < 16) ? sQI[r*17 + lane] : ((r == lane-16) ? 1.f : 0.f);
#pragma unroll
                for (int p = 0; p < 16; p++) {
                    float piv = __shfl_sync(0xffffffffu, creg[p], p);
                    float newp = creg[p] * (1.0f / piv);
#pragma unroll
                    for (int r = 0; r < 16; r++) {
                        if (r == p) continue;
                        float fac = __shfl_sync(0xffffffffu, creg[r], p);
                        creg[r] = fmaf(-fac, newp, creg[r]);
                    }
                    creg[p] = newp;
                }
                if (lane >= 16) {
#pragma unroll
                    for (int r = 0; r < 16; r++) sQI[r*17 + (lane-16)] = creg[r];
                }
            } else if (tid >= 64 && tid < 128) {
                const int j = tid - 64; float acc = 0.f;
#pragma unroll 8
                for (int i = 0; i < 64; i++) acc = fmaf(sA[i*64+j], vq2[i], acc);
                vlx[j] = vrx[j] + vv[j] + DTc*acc;
            } else if (tid >= 128 && tid < 144) {
                const int j = tid - 128; float acc = 0.f;
#pragma unroll 8
                for (int i = 0; i < 64; i++) acc = fmaf(sBm[i*16+j], vq2[i], acc);
                vlu[j] = vru[j] + DTc*acc;
            }
            __syncthreads();
            // S6: K = -Inv @ Qxu^T ; k = -Inv @ lu
            {
                const int i = tid & 15, m0 = (tid >> 4) * 4;
                float a0=0.f,a1=0.f,a2=0.f,a3=0.f;
#pragma unroll
                for (int j = 0; j < 16; j++) {
                    const float iv = sQI[i*17+j];
                    a0 = fmaf(iv, sQxu[(m0+0)*16+j], a0);
                    a1 = fmaf(iv, sQxu[(m0+1)*16+j], a1);
                    a2 = fmaf(iv, sQxu[(m0+2)*16+j], a2);
                    a3 = fmaf(iv, sQxu[(m0+3)*16+j], a3);
                }
                sK[i*64+m0]=-a0; sK[i*64+m0+1]=-a1; sK[i*64+m0+2]=-a2; sK[i*64+m0+3]=-a3;
            }
            if (tid < 16) {
                float a = 0.f;
#pragma unroll
                for (int j = 0; j < 16; j++) a = fmaf(sQI[tid*17+j], vlu[j], a);
                vkk[tid] = -a;
            }
            __syncthreads();
            // S7: Pn = Qxx + Qxu@K, in place into sP
            gemmPnf2(sP, sQxu, sK, sP);
            __syncthreads();
            // S8: symmetrize + spill g_P (pair ownership, direct stores), sn, kv, K spill
            {
                float* gp = g_P + (size_t)ofs*4096;
                for (int e = tid; e < 4096; e += 256) {
                    int i = e >> 6, j = e & 63;
                    if (i < j) {
                        float m = 0.5f * (sP[e] + sP[j*64+i]);
                        sP[e] = m; sP[j*64+i] = m;
                        gp[e] = m; gp[j*64+i] = m;
                    } else if (i == j) {
                        gp[e] = sP[e];
                    }
                }
            }
            if (tid < 64) {
                const int j = tid; float a = vlx[j];
#pragma unroll
                for (int s = 0; s < 16; s++) {
                    int i = ((j>>1) + s) & 15;
                    a = fmaf(sQxu[j*16+i], vkk[i], a);
                }
                vsv[j] = a; g_s[ofs*64+j] = a;
            } else if (tid < 80) {
                g_kv[ofs*16 + tid-64] = vkk[tid-64];
            }
            ((float4*)(g_K + (size_t)ofs*1024))[tid] = ((const float4*)sK)[tid];
            __syncthreads();
        }

        // ---------------- forward rollout ----------------
        if (tid < 64) vdx[tid] = -vx0r[tid];
        __syncthreads();
        for (int n = 0; n < 64; n++) {
            const int ofs = n*256 + b;
            // load P, K, s2, xres
            for (int e = tid; e < 1024; e += 256)
                ((float4*)sM1)[e] = ((const float4*)(g_P + (size_t)ofs*4096))[e];
            ((float4*)sK)[tid] = ((const float4*)(g_K + (size_t)ofs*1024))[tid];
            if (tid < 64) { vs2[tid] = g_s2[ofs*64+tid]; vxres[tid] = g_xres[ofs*64+tid]; }
            __syncthreads();
            // phase1: adx/pdx partials (all); du partials (tid<64)
            {
                const int j = tid & 63, qt = tid >> 6;
                float aa = 0.f, pp = 0.f;
#pragma unroll
                for (int s = 0; s < 16; s++) {
                    int i = qt*16 + s;
                    aa = fmaf(sAT[i*64+j], vdx[i], aa);
                    pp = fmaf(sM1[i*64+j], vdx[i], pp);
                }
                sRed[qt*64+j] = aa; sRedB[qt*64+j] = pp;
            }
            if (tid < 64) {
                const int i = tid & 15, qs = tid >> 4;
                float a = 0.f;
#pragma unroll
                for (int s = 0; s < 16; s++) {
                    int m = qs*16 + ((i + s) & 15);
                    a = fmaf(sK[i*64+m], vdx[m], a);
                }
                sRedC[qs*16+i] = a;
            }
            __syncthreads();
            // phase2: reduce du
            if (tid < 16) {
                vdu[tid] = g_kv[ofs*16+tid] + sRedC[tid] + sRedC[16+tid] + sRedC[32+tid] + sRedC[48+tid];
            }
            __syncthreads();
            // phase3: finalize
            if (tid < 64) {
                const int j = tid;
                float ax = sRed[j] + sRed[64+j] + sRed[128+j] + sRed[192+j];
                float px = sRedB[j] + sRedB[64+j] + sRedB[128+j] + sRedB[192+j];
                float bdu = 0.f;
#pragma unroll
                for (int i = 0; i < 16; i++) bdu = fmaf(sBmT[i*64+j], vdu[i], bdu);
                float old = vdx[j];
                const int idx = ofs*64 + j;
                xw[idx] += old;
                lw[idx] += px + g_s[ofs*64+j];
                vdx[j] = old + DTc*vs2[j]*(ax + bdu) + vxres[j];
            } else if (tid < 80) {
                uw[ofs*16 + tid-64] += vdu[tid-64];
            }
            __syncthreads();
        }
        // terminal: dlmd_N = Vf dxN + rN
        if (tid < 64) {
            const int j = tid; float p = 0.f;
#pragma unroll 8
            for (int i = 0; i < 64; i++) p = fmaf(Vf_in[i*64+j], vdx[i], p);
            const int idx = (64*256 + b)*64 + j;
            xw[idx] += vdx[j];
            lw[idx] += p + vrN[j];
        }
        __syncthreads();
    }
}

extern "C" void kernel_launch(void* const* d_in, const int* in_sizes, int n_in,
                              void* d_out, int out_size) {
    const float* x0   = (const float*)d_in[0];
    const float* x    = (const float*)d_in[1];
    const float* u    = (const float*)d_in[2];
    const float* lmd  = (const float*)d_in[3];
    const float* A    = (const float*)d_in[4];
    const float* Bm   = (const float*)d_in[5];
    const float* Qx   = (const float*)d_in[6];
    const float* R    = (const float*)d_in[7];
    const float* Vf   = (const float*)d_in[8];
    const float* xref = (const float*)d_in[9];
    const int smem_bytes = 111488;
    cudaFuncSetAttribute(mpc_kernel, cudaFuncAttributeMaxDynamicSharedMemorySize, smem_bytes);
    mpc_kernel<<<256, 256, smem_bytes>>>(x0, x, u, lmd, A, Bm, Qx, R, Vf, xref, (float*)d_out);
}

// round 5
// speedup vs baseline: 1.7498x; 1.1160x over previous
#include <cuda_runtime.h>

#define DTc 0.05f
typedef unsigned long long ull;

// global scratch (static device arrays; no allocation)
__device__ float g_s2  [64*256*64];
__device__ float g_xres[64*256*64];
__device__ float g_K   [64*256*16*64];
__device__ float g_kv  [64*256*16];
__device__ float g_s   [64*256*64];
__device__ float g_P   [(size_t)64*256*64*64];

__device__ __forceinline__ ull pack2(float x, float y) {
    ull r; asm("mov.b64 %0, {%1, %2};" : "=l"(r) : "f"(x), "f"(y)); return r;
}
__device__ __forceinline__ void unpack2(ull v, float& x, float& y) {
    asm("mov.b64 {%0, %1}, %2;" : "=f"(x), "=f"(y) : "l"(v));
}
__device__ __forceinline__ void ffma2(ull& d, ull a, ull b) {
    asm("fma.rn.f32x2 %0, %1, %2, %0;" : "+l"(d) : "l"(a), "l"(b));
}

// map t in [0,136) -> lower-tri tile (R,C), R>=C, 16x16 tile grid
__device__ __forceinline__ void tri_map(int t, int& R, int& C) {
    float f = sqrtf(8.f*(float)t + 1.f);
    R = (int)((f - 1.f) * 0.5f);
    C = t - ((R*(R+1)) >> 1);
    if (C > R) { R++; C = t - ((R*(R+1)) >> 1); }
    else if (C < 0) { R--; C = t - ((R*(R+1)) >> 1); }
}

// C(64x64) = [A1] + [A2] + alpha * (L K-scaled-by-s) @ R. 256 thr, 4x4 tiles, f32x2.
template<bool SCALE>
__device__ __forceinline__ void gemm64f2(float* __restrict__ C,
    const float* __restrict__ L, const float* __restrict__ R,
    const float* __restrict__ s, float alpha,
    const float* __restrict__ A1, const float* __restrict__ A2)
{
    const int tid = threadIdx.x;
    const int c0 = (tid & 15) * 4, r0 = (tid >> 4) * 4;
    ull acc[4][2];
#pragma unroll
    for (int r = 0; r < 4; r++) { acc[r][0] = 0ull; acc[r][1] = 0ull; }
#pragma unroll 4
    for (int jj = 0; jj < 16; jj++) {
        float4 sv4;
        if (SCALE) sv4 = *(const float4*)(s + jj*4);
        const float* sp = (const float*)&sv4;
        float4 lv[4], rv[4];
#pragma unroll
        for (int r = 0; r < 4; r++) lv[r] = *(const float4*)(L + (r0+r)*64 + jj*4);
#pragma unroll
        for (int q = 0; q < 4; q++) rv[q] = *(const float4*)(R + (jj*4+q)*64 + c0);
        ull rp[4][2];
#pragma unroll
        for (int q = 0; q < 4; q++) {
            rp[q][0] = pack2(rv[q].x, rv[q].y);
            rp[q][1] = pack2(rv[q].z, rv[q].w);
        }
#pragma unroll
        for (int r = 0; r < 4; r++) {
            const float* lp = (const float*)&lv[r];
#pragma unroll
            for (int q = 0; q < 4; q++) {
                float m = SCALE ? lp[q]*sp[q] : lp[q];
                ull lb = pack2(m, m);
                ffma2(acc[r][0], lb, rp[q][0]);
                ffma2(acc[r][1], lb, rp[q][1]);
            }
        }
    }
#pragma unroll
    for (int r = 0; r < 4; r++) {
        float o[4];
        unpack2(acc[r][0], o[0], o[1]);
        unpack2(acc[r][1], o[2], o[3]);
        const int base = (r0+r)*64 + c0;
#pragma unroll
        for (int c = 0; c < 4; c++) {
            float v = alpha * o[c];
            if (A1) v += A1[base+c];
            if (A2) v += A2[base+c];
            C[base+c] = v;
        }
    }
}

// C(64x16) = [A1] + alpha * (L K-scaled-by-s)(64x64) @ R(64x16). 256 threads.
template<bool SCALE>
__device__ __forceinline__ void gemm6416f2(float* __restrict__ C,
    const float* __restrict__ L, const float* __restrict__ R,
    const float* __restrict__ s, float alpha, const float* __restrict__ A1)
{
    const int tid = threadIdx.x;
    const int c = tid & 15, r0 = (tid >> 4) * 4;
    ull acc01 = 0ull, acc23 = 0ull;
#pragma unroll 4
    for (int jj = 0; jj < 16; jj++) {
        float4 sv4;
        if (SCALE) sv4 = *(const float4*)(s + jj*4);
        const float* sp = (const float*)&sv4;
        float4 lv[4];
#pragma unroll
        for (int r = 0; r < 4; r++) lv[r] = *(const float4*)(L + (r0+r)*64 + jj*4);
#pragma unroll
        for (int q = 0; q < 4; q++) {
            float rb = R[(jj*4+q)*16 + c];
            ull rbb = pack2(rb, rb);
            float f0 = ((const float*)&lv[0])[q], f1 = ((const float*)&lv[1])[q];
            float f2 = ((const float*)&lv[2])[q], f3 = ((const float*)&lv[3])[q];
            if (SCALE) { f0*=sp[q]; f1*=sp[q]; f2*=sp[q]; f3*=sp[q]; }
            ffma2(acc01, pack2(f0, f1), rbb);
            ffma2(acc23, pack2(f2, f3), rbb);
        }
    }
    float o[4];
    unpack2(acc01, o[0], o[1]);
    unpack2(acc23, o[2], o[3]);
#pragma unroll
    for (int r = 0; r < 4; r++) {
        float v = alpha * o[r];
        if (A1) v += A1[(r0+r)*16 + c];
        C[(r0+r)*16 + c] = v;
    }
}

// one 4x4 tile of Qxx at (r0,c0): C = A1 + A2 + DT*(LT rows, K-scaled) @ Rm; mirror if mir
__device__ __forceinline__ void qxx_tile(float* __restrict__ C,
    const float* __restrict__ LT, const float* __restrict__ Rm,
    const float* __restrict__ s, const float* __restrict__ A1,
    const float* __restrict__ A2, int r0, int c0, bool mir)
{
    ull acc[4][2];
#pragma unroll
    for (int r = 0; r < 4; r++) { acc[r][0] = 0ull; acc[r][1] = 0ull; }
#pragma unroll 4
    for (int jj = 0; jj < 16; jj++) {
        float4 sv4 = *(const float4*)(s + jj*4);
        const float* sp = (const float*)&sv4;
        float4 lv[4], rv[4];
#pragma unroll
        for (int r = 0; r < 4; r++) lv[r] = *(const float4*)(LT + (r0+r)*64 + jj*4);
#pragma unroll
        for (int q = 0; q < 4; q++) rv[q] = *(const float4*)(Rm + (jj*4+q)*64 + c0);
        ull rp[4][2];
#pragma unroll
        for (int q = 0; q < 4; q++) {
            rp[q][0] = pack2(rv[q].x, rv[q].y);
            rp[q][1] = pack2(rv[q].z, rv[q].w);
        }
#pragma unroll
        for (int r = 0; r < 4; r++) {
            const float* lp = (const float*)&lv[r];
#pragma unroll
            for (int q = 0; q < 4; q++) {
                float m = lp[q]*sp[q];
                ull lb = pack2(m, m);
                ffma2(acc[r][0], lb, rp[q][0]);
                ffma2(acc[r][1], lb, rp[q][1]);
            }
        }
    }
#pragma unroll
    for (int r = 0; r < 4; r++) {
        float o[4];
        unpack2(acc[r][0], o[0], o[1]);
        unpack2(acc[r][1], o[2], o[3]);
        const int base = (r0+r)*64 + c0;
#pragma unroll
        for (int c = 0; c < 4; c++) {
            float v = DTc*o[c] + A1[base+c] + A2[base+c];
            C[base+c] = v;
            if (mir) C[(c0+c)*64 + (r0+r)] = v;
        }
    }
}

// one 4x4 tile of Pn at (r0,c0): C = A1 + L(64x16)@R(16x64); in place, mirror if mir
__device__ __forceinline__ void pn_tile(float* __restrict__ C,
    const float* __restrict__ L, const float* __restrict__ R,
    int r0, int c0, bool mir)
{
    ull acc[4][2];
#pragma unroll
    for (int r = 0; r < 4; r++) { acc[r][0] = 0ull; acc[r][1] = 0ull; }
#pragma unroll
    for (int jj = 0; jj < 4; jj++) {
        float4 lv[4], rv[4];
#pragma unroll
        for (int r = 0; r < 4; r++) lv[r] = *(const float4*)(L + (r0+r)*16 + jj*4);
#pragma unroll
        for (int q = 0; q < 4; q++) rv[q] = *(const float4*)(R + (jj*4+q)*64 + c0);
        ull rp[4][2];
#pragma unroll
        for (int q = 0; q < 4; q++) {
            rp[q][0] = pack2(rv[q].x, rv[q].y);
            rp[q][1] = pack2(rv[q].z, rv[q].w);
        }
#pragma unroll
        for (int r = 0; r < 4; r++) {
            const float* lp = (const float*)&lv[r];
#pragma unroll
            for (int q = 0; q < 4; q++) {
                ull lb = pack2(lp[q], lp[q]);
                ffma2(acc[r][0], lb, rp[q][0]);
                ffma2(acc[r][1], lb, rp[q][1]);
            }
        }
    }
#pragma unroll
    for (int r = 0; r < 4; r++) {
        float o[4];
        unpack2(acc[r][0], o[0], o[1]);
        unpack2(acc[r][1], o[2], o[3]);
        const int base = (r0+r)*64 + c0;
#pragma unroll
        for (int c = 0; c < 4; c++) {
            float v = C[base+c] + o[c];
            C[base+c] = v;
            if (mir) C[(c0+c)*64 + (r0+r)] = v;
        }
    }
}

__global__ void __launch_bounds__(256, 2) mpc_kernel(
    const float* __restrict__ x0_in, const float* __restrict__ x_in,
    const float* __restrict__ u_in,  const float* __restrict__ lmd_in,
    const float* __restrict__ A_in,  const float* __restrict__ Bm_in,
    const float* __restrict__ Qx_in, const float* __restrict__ R_in,
    const float* __restrict__ Vf_in, const float* __restrict__ xref_in,
    float* __restrict__ out)
{
    extern __shared__ float sh[];
    float* sA   = sh;            float* sAT  = sA+4096;   float* sQx = sAT+4096;
    float* sP   = sQx+4096;      float* sM1  = sP+4096;
    float* sBm  = sM1+4096;      float* sBmT = sBm+1024;  float* sPFu= sBmT+1024;
    float* sQxu = sPFu+1024;     float* sK   = sQxu+1024;
    float* sR   = sK+1024;       float* sRed = sR+256;    float* sRedB = sRed+256;
    float* sRedC= sRedB+256;     // 64
    float* vxref= sRedC+64;
    float* vrN  = vxref+64; float* vx0r = vrN+64;  float* vs2  = vx0r+64;
    float* vxres= vs2+64;   float* vsv  = vxres+64;float* vxn  = vsv+64;
    float* vxn1 = vxn+64;   float* vlmd0= vxn1+64; float* vlmd1= vlmd0+64;
    float* vq   = vlmd1+64; float* vxmr = vq+64;   float* vrx  = vxmr+64;
    float* vv   = vrx+64;   float* vq2  = vv+64;   float* vlx  = vq2+64;
    float* vdx  = vlx+64;
    float* sQI  = vdx+64;   // 272 (17-stride: Quu then Inv)
    float* vu   = sQI+272;  float* vru  = vu+16;   float* vlu  = vru+16;
    float* vkk  = vlu+16;   float* vdu  = vkk+16;

    const int tid = threadIdx.x, b = blockIdx.x;
    float* xw = out;
    float* uw = out + 65*256*64;
    float* lw = uw  + 64*256*16;

    for (int e = tid; e < 4096; e += 256) {
        float a = A_in[e];
        sA[e] = a; sQx[e] = Qx_in[e];
        int i = e >> 6, j = e & 63;
        sAT[j*64+i] = a;
    }
    for (int e = tid; e < 1024; e += 256) {
        float v = Bm_in[e]; sBm[e] = v;
        int j = e >> 4, i = e & 15;
        sBmT[i*64+j] = v;
    }
    sR[tid] = R_in[tid];
    if (tid < 64) vxref[tid] = xref_in[tid];
    for (int e = tid; e < 65*64; e += 256) {
        int n = e >> 6, i = e & 63;
        int idx = (n*256 + b)*64 + i;
        xw[idx] = x_in[idx]; lw[idx] = lmd_in[idx];
    }
    for (int e = tid; e < 64*16; e += 256) {
        int n = e >> 4, i = e & 15;
        int idx = (n*256 + b)*16 + i;
        uw[idx] = u_in[idx];
    }
    __syncthreads();

    // lower-tri tile coords for this thread (tid < 136)
    int TR, TC;
    tri_map(tid < 136 ? tid : 0, TR, TC);
    const int tr0 = TR*4, tc0 = TC*4;
    const bool tmir = (TR != TC);

    for (int iter = 0; iter < 2; iter++) {
        // terminal: P_N = Vf, rN = Vf(x_N - xref) - lmd_N, s_N = rN
        for (int e = tid; e < 4096; e += 256) sP[e] = Vf_in[e];
        if (tid < 64) {
            vxn[tid]  = xw[(64*256 + b)*64 + tid];
            vx0r[tid] = xw[b*64 + tid] - x0_in[b*64 + tid];
        }
        __syncthreads();
        if (tid < 64) {
            const int j = tid; float acc = 0.f;
#pragma unroll 8
            for (int i = 0; i < 64; i++) acc = fmaf(sP[i*64+j], vxn[i]-vxref[i], acc);
            float r = acc - lw[(64*256 + b)*64 + j];
            vrN[j] = r; vsv[j] = r;
        }
        __syncthreads();

        // ---------------- backward Riccati ----------------
        for (int n = 63; n >= 0; n--) {
            const int ofs = n*256 + b;
            // A: spill prev P (coalesced float4) + load step vectors
            if (n < 63) {
                float4* gp = (float4*)(g_P + (size_t)(ofs+256)*4096);
#pragma unroll
                for (int e = tid; e < 1024; e += 256) gp[e] = ((const float4*)sP)[e];
            }
            if (tid < 64) {
                vxn[tid]   = xw[ofs*64 + tid];
                vxn1[tid]  = xw[(ofs+256)*64 + tid];
                vlmd0[tid] = lw[ofs*64 + tid];
                vlmd1[tid] = lw[(ofs+256)*64 + tid];
            } else if (tid < 80) {
                vu[tid-64] = uw[ofs*16 + tid-64];
            }
            __syncthreads();
            // B: z partials (4-way split)
            {
                const int j = tid & 63, qt = tid >> 6;
                float a = 0.f;
#pragma unroll
                for (int s = 0; s < 16; s++) {
                    int i = qt*16 + s;
                    a = fmaf(sAT[i*64+j], vxn[i], a);
                }
                if (qt == 3) {
#pragma unroll
                    for (int i = 0; i < 16; i++) a = fmaf(sBmT[i*64+j], vu[i], a);
                }
                sRed[qt*64+j] = a;
            }
            __syncthreads();
            // C: finish z -> s2, xres, q, xmr
            if (tid < 64) {
                const int j = tid;
                float z = sRed[j] + sRed[64+j] + sRed[128+j] + sRed[192+j];
                float t = tanhf(z), s2 = 1.f - t*t;
                vs2[j] = s2;
                float xr = vxn[j] + DTc*t - vxn1[j];
                vxres[j] = xr;
                vq[j]   = s2 * vlmd1[j];
                vxmr[j] = vxn[j] - vxref[j];
                g_s2[ofs*64+j] = s2; g_xres[ofs*64+j] = xr;
            }
            __syncthreads();
            // D: PFx -> sM1, PFu -> sPFu, then rx/ru/v matvecs (independent of gemm outputs)
            gemm64f2<true>(sM1, sP, sA, vs2, DTc, sP, 0);
            gemm6416f2<true>(sPFu, sP, sBm, vs2, DTc, 0);
            if (tid < 64) {
                const int j = tid; float a1 = 0.f, a2 = 0.f;
#pragma unroll 8
                for (int i = 0; i < 64; i++) {
                    a1 = fmaf(sQx[i*64+j], vxmr[i], a1);
                    a2 = fmaf(sA[i*64+j],  vq[i],   a2);
                }
                vrx[j] = a1 + vlmd1[j] + DTc*a2 - vlmd0[j];
            } else if (tid < 80) {
                const int j = tid - 64; float a1 = 0.f, a2 = 0.f;
#pragma unroll
                for (int i = 0; i < 16; i++) a1 = fmaf(sR[i*16+j], vu[i], a1);
#pragma unroll 8
                for (int i = 0; i < 64; i++) a2 = fmaf(sBm[i*16+j], vq[i], a2);
                vru[j] = a1 + DTc*a2;
            } else if (tid >= 128 && tid < 192) {
                const int j = tid - 128; float acc = 0.f;
#pragma unroll 8
                for (int i = 0; i < 64; i++) acc = fmaf(sP[i*64+j], vxres[i], acc);
                float vv_ = acc + vsv[j];
                vv[j] = vv_; vq2[j] = vs2[j] * vv_;
            }
            __syncthreads();
            // E: Qxx lower-tri (tid<136) -> sP in place + mirror; Qxu (136..199); Quu (200..231)
            if (tid < 136) {
                qxx_tile(sP, sAT, sM1, vs2, sQx, sM1, tr0, tc0, tmir);
            } else if (tid < 200) {
                const int t = tid - 136;
                const int c0 = (t & 3) * 4, r0 = (t >> 2) * 4;
                ull a01[4]; // per row: 2 ull for 4 cols
                ull a23[4];
#pragma unroll
                for (int r = 0; r < 4; r++) { a01[r] = 0ull; a23[r] = 0ull; }
#pragma unroll 4
                for (int jj = 0; jj < 16; jj++) {
                    float4 sv4 = *(const float4*)(vs2 + jj*4);
                    const float* sp = (const float*)&sv4;
                    float4 lv[4], rv[4];
#pragma unroll
                    for (int r = 0; r < 4; r++) lv[r] = *(const float4*)(sAT + (r0+r)*64 + jj*4);
#pragma unroll
                    for (int q = 0; q < 4; q++) rv[q] = *(const float4*)(sPFu + (jj*4+q)*16 + c0);
                    ull rp[4][2];
#pragma unroll
                    for (int q = 0; q < 4; q++) {
                        rp[q][0] = pack2(rv[q].x, rv[q].y);
                        rp[q][1] = pack2(rv[q].z, rv[q].w);
                    }
#pragma unroll
                    for (int r = 0; r < 4; r++) {
                        const float* lp = (const float*)&lv[r];
#pragma unroll
                        for (int q = 0; q < 4; q++) {
                            float m = lp[q]*sp[q];
                            ull lb = pack2(m, m);
                            ffma2(a01[r], lb, rp[q][0]);
                            ffma2(a23[r], lb, rp[q][1]);
                        }
                    }
                }
#pragma unroll
                for (int r = 0; r < 4; r++) {
                    float o[4];
                    unpack2(a01[r], o[0], o[1]);
                    unpack2(a23[r], o[2], o[3]);
#pragma unroll
                    for (int c = 0; c < 4; c++)
                        sQxu[(r0+r)*16 + c0+c] = sPFu[(r0+r)*16 + c0+c] + DTc*o[c];
                }
            } else if (tid < 232) {
                const int q = tid - 200;
                const int i = q >> 1, k0 = (q & 1) * 8;
                float acc[8] = {0,0,0,0,0,0,0,0};
#pragma unroll 8
                for (int j = 0; j < 64; j++) {
                    float l = sBmT[i*64+j] * vs2[j];
#pragma unroll
                    for (int k = 0; k < 8; k++)
                        acc[k] = fmaf(l, sPFu[j*16 + k0 + k], acc[k]);
                }
#pragma unroll
                for (int k = 0; k < 8; k++)
                    sQI[i*17 + k0 + k] = sR[i*16 + k0 + k] + DTc*acc[k];
            }
            __syncthreads();
            // F: warp0 shuffle GJ inverse of Quu || lx || lu
            if (tid < 32) {
                const int lane = tid;
                float creg[16];
#pragma unroll
                for (int r = 0; r < 16; r++)
                    creg[r] = (lane < 16) ? sQI[r*17 + lane] : ((r == lane-16) ? 1.f : 0.f);
#pragma unroll
                for (int p = 0; p < 16; p++) {
                    float piv = __shfl_sync(0xffffffffu, creg[p], p);
                    float newp = creg[p] * (1.0f / piv);
#pragma unroll
                    for (int r = 0; r < 16; r++) {
                        if (r == p) continue;
                        float fac = __shfl_sync(0xffffffffu, creg[r], p);
                        creg[r] = fmaf(-fac, newp, creg[r]);
                    }
                    creg[p] = newp;
                }
                if (lane >= 16) {
#pragma unroll
                    for (int r = 0; r < 16; r++) sQI[r*17 + (lane-16)] = creg[r];
                }
            } else if (tid >= 64 && tid < 128) {
                const int j = tid - 64; float acc = 0.f;
#pragma unroll 8
                for (int i = 0; i < 64; i++) acc = fmaf(sA[i*64+j], vq2[i], acc);
                vlx[j] = vrx[j] + vv[j] + DTc*acc;
            } else if (tid >= 128 && tid < 144) {
                const int j = tid - 128; float acc = 0.f;
#pragma unroll 8
                for (int i = 0; i < 64; i++) acc = fmaf(sBm[i*16+j], vq2[i], acc);
                vlu[j] = vru[j] + DTc*acc;
            }
            __syncthreads();
            // G: K = -Inv @ Qxu^T (+ direct g_K store) ; k = -Inv @ lu (+ g_kv store)
            {
                const int i = tid & 15, m0 = (tid >> 4) * 4;
                float a0=0.f,a1=0.f,a2=0.f,a3=0.f;
#pragma unroll
                for (int j = 0; j < 16; j++) {
                    const float iv = sQI[i*17+j];
                    a0 = fmaf(iv, sQxu[(m0+0)*16+j], a0);
                    a1 = fmaf(iv, sQxu[(m0+1)*16+j], a1);
                    a2 = fmaf(iv, sQxu[(m0+2)*16+j], a2);
                    a3 = fmaf(iv, sQxu[(m0+3)*16+j], a3);
                }
                sK[i*64+m0]=-a0; sK[i*64+m0+1]=-a1; sK[i*64+m0+2]=-a2; sK[i*64+m0+3]=-a3;
                float4 kv4 = make_float4(-a0, -a1, -a2, -a3);
                ((float4*)(g_K + (size_t)ofs*1024))[i*16 + (m0>>2)] = kv4;
            }
            if (tid < 16) {
                float a = 0.f;
#pragma unroll
                for (int j = 0; j < 16; j++) a = fmaf(sQI[tid*17+j], vlu[j], a);
                vkk[tid] = -a;
                g_kv[ofs*16 + tid] = -a;
            }
            __syncthreads();
            // H: Pn lower-tri in place (+mirror) ; sn (136..199) + g_s
            if (tid < 136) {
                pn_tile(sP, sQxu, sK, tr0, tc0, tmir);
            } else if (tid < 200) {
                const int j = tid - 136; float a = vlx[j];
#pragma unroll
                for (int s = 0; s < 16; s++) {
                    int i = ((j>>1) + s) & 15;
                    a = fmaf(sQxu[j*16+i], vkk[i], a);
                }
                vsv[j] = a; g_s[ofs*64+j] = a;
            }
            __syncthreads();
        }
        // spill P_0
        {
            float4* gp = (float4*)(g_P + (size_t)(0*256 + b)*4096);
#pragma unroll
            for (int e = tid; e < 1024; e += 256) gp[e] = ((const float4*)sP)[e];
        }

        // ---------------- forward rollout ----------------
        if (tid < 64) vdx[tid] = -vx0r[tid];
        __syncthreads();
        for (int n = 0; n < 64; n++) {
            const int ofs = n*256 + b;
            for (int e = tid; e < 1024; e += 256)
                ((float4*)sM1)[e] = ((const float4*)(g_P + (size_t)ofs*4096))[e];
            ((float4*)sK)[tid] = ((const float4*)(g_K + (size_t)ofs*1024))[tid];
            if (tid < 64) { vs2[tid] = g_s2[ofs*64+tid]; vxres[tid] = g_xres[ofs*64+tid]; }
            __syncthreads();
            // phase1: adx/pdx partials (all); du partials (tid<64)
            {
                const int j = tid & 63, qt = tid >> 6;
                float aa = 0.f, pp = 0.f;
#pragma unroll
                for (int s = 0; s < 16; s++) {
                    int i = qt*16 + s;
                    aa = fmaf(sAT[i*64+j], vdx[i], aa);
                    pp = fmaf(sM1[i*64+j], vdx[i], pp);
                }
                sRed[qt*64+j] = aa; sRedB[qt*64+j] = pp;
            }
            if (tid < 64) {
                const int i = tid & 15, qs = tid >> 4;
                float a = 0.f;
#pragma unroll
                for (int s = 0; s < 16; s++) {
                    int m = qs*16 + ((i + s) & 15);
                    a = fmaf(sK[i*64+m], vdx[m], a);
                }
                sRedC[qs*16+i] = a;
            }
            __syncthreads();
            if (tid < 16) {
                vdu[tid] = g_kv[ofs*16+tid] + sRedC[tid] + sRedC[16+tid] + sRedC[32+tid] + sRedC[48+tid];
            }
            __syncthreads();
            if (tid < 64) {
                const int j = tid;
                float ax = sRed[j] + sRed[64+j] + sRed[128+j] + sRed[192+j];
                float px = sRedB[j] + sRedB[64+j] + sRedB[128+j] + sRedB[192+j];
                float bdu = 0.f;
#pragma unroll
                for (int i = 0; i < 16; i++) bdu = fmaf(sBmT[i*64+j], vdu[i], bdu);
                float old = vdx[j];
                const int idx = ofs*64 + j;
                xw[idx] += old;
                lw[idx] += px + g_s[ofs*64+j];
                vdx[j] = old + DTc*vs2[j]*(ax + bdu) + vxres[j];
            } else if (tid < 80) {
                uw[ofs*16 + tid-64] += vdu[tid-64];
            }
            __syncthreads();
        }
        // terminal: dlmd_N = Vf dxN + rN
        if (tid < 64) {
            const int j = tid; float p = 0.f;
#pragma unroll 8
            for (int i = 0; i < 64; i++) p = fmaf(Vf_in[i*64+j], vdx[i], p);
            const int idx = (64*256 + b)*64 + j;
            xw[idx] += vdx[j];
            lw[idx] += p + vrN[j];
        }
        __syncthreads();
    }
}

extern "C" void kernel_launch(void* const* d_in, const int* in_sizes, int n_in,
                              void* d_out, int out_size) {
    const float* x0   = (const float*)d_in[0];
    const float* x    = (const float*)d_in[1];
    const float* u    = (const float*)d_in[2];
    const float* lmd  = (const float*)d_in[3];
    const float* A    = (const float*)d_in[4];
    const float* Bm   = (const float*)d_in[5];
    const float* Qx   = (const float*)d_in[6];
    const float* R    = (const float*)d_in[7];
    const float* Vf   = (const float*)d_in[8];
    const float* xref = (const float*)d_in[9];
    const int smem_bytes = 111488;
    cudaFuncSetAttribute(mpc_kernel, cudaFuncAttributeMaxDynamicSharedMemorySize, smem_bytes);
    mpc_kernel<<<256, 256, smem_bytes>>>(x0, x, u, lmd, A, Bm, Qx, R, Vf, xref, (float*)d_out);
}